// round 4
// baseline (speedup 1.0000x reference)
#include <cuda_runtime.h>
#include <math.h>

#define BB 64      // batch
#define SS 64      // seq / timesteps
#define IN 512     // input dim
#define HH 512     // hidden dim
#define G4 2048    // 4*H
#define NBLK 128   // persistent blocks for phase 2 (1 CTA/SM, all resident)

typedef unsigned long long ull;

// ---------------- packed fp32x2 helpers (sm_103a FFMA2 path) ----------------
__device__ __forceinline__ void ffma2(ull& d, ull a, ull b) {
    asm("fma.rn.f32x2 %0, %1, %2, %0;" : "+l"(d) : "l"(a), "l"(b));
}
__device__ __forceinline__ ull pk2(float x, float y) {
    ull r; asm("mov.b64 %0, {%1, %2};" : "=l"(r) : "f"(x), "f"(y)); return r;
}
__device__ __forceinline__ float2 upk2(ull v) {
    float2 r; asm("mov.b64 {%0, %1}, %2;" : "=f"(r.x), "=f"(r.y) : "l"(v)); return r;
}

// ---------------- scratch (device globals; no allocation APIs) ----------------
__device__ float g_Gx[(size_t)SS * G4 * BB];   // [s][j][b], 33.5 MB
__device__ float g_h[2][BB * HH];              // double-buffered hidden state
__device__ unsigned int g_bar_cnt = 0;
__device__ volatile unsigned int g_bar_gen = 0;

// ---------------- grid-wide barrier (all NBLK blocks resident) ----------------
__device__ __forceinline__ void grid_sync_all() {
    __syncthreads();
    if (threadIdx.x == 0) {
        unsigned int gen = g_bar_gen;
        __threadfence();
        if (atomicAdd(&g_bar_cnt, 1u) == NBLK - 1) {
            g_bar_cnt = 0;
            __threadfence();
            g_bar_gen = gen + 1;
        } else {
            while (g_bar_gen == gen) { __nanosleep(32); }
        }
        __threadfence();
    }
    __syncthreads();
}

// =====================================================================
// Phase 1: Gx[s][j][b] = sum_k x[b][s][k] * W_ih[s][j][k]
// grid (32 j-tiles, 64 s), 256 threads, 64x64 tile, Ktile=32,
// 4x4 microtile done as 2x4 packed-f32x2 accumulators (FFMA2).
// =====================================================================
__global__ __launch_bounds__(256) void gemm_x_kernel(
    const float* __restrict__ x, const float* __restrict__ Wih) {
    __shared__ float As[32][64];   // [k][b]
    __shared__ float Bs[32][64];   // [k][j]

    const int s   = blockIdx.y;
    const int j0  = blockIdx.x * 64;
    const int tid = threadIdx.x;
    const int ty  = tid >> 4;   // b-group 0..15
    const int tx  = tid & 15;   // j-group 0..15

    const float* xA = x + (size_t)s * IN;
    const float* wB = Wih + ((size_t)s * G4 + j0) * IN;

    ull acc2[2][4];   // acc2[p][j] packs (acc[2p][j], acc[2p+1][j])
#pragma unroll
    for (int p = 0; p < 2; p++)
#pragma unroll
        for (int j = 0; j < 4; j++) acc2[p][j] = 0ull;   // (0.f, 0.f)

    for (int k0 = 0; k0 < IN; k0 += 32) {
#pragma unroll
        for (int p = 0; p < 2; p++) {
            int fi = tid * 2 + p;          // 0..511 float4 index
            int r  = fi >> 3;              // row 0..63
            int kk = (fi & 7) << 2;        // k within chunk
            float4 va = *(const float4*)(xA + (size_t)r * (SS * IN) + k0 + kk);
            As[kk + 0][r] = va.x; As[kk + 1][r] = va.y;
            As[kk + 2][r] = va.z; As[kk + 3][r] = va.w;
            float4 vb = *(const float4*)(wB + (size_t)r * IN + k0 + kk);
            Bs[kk + 0][r] = vb.x; Bs[kk + 1][r] = vb.y;
            Bs[kk + 2][r] = vb.z; Bs[kk + 3][r] = vb.w;
        }
        __syncthreads();
#pragma unroll
        for (int k = 0; k < 32; k++) {
            ulonglong2 a2 = *(const ulonglong2*)&As[k][ty << 2]; // (a0,a1),(a2,a3)
            float4 bv = *(const float4*)&Bs[k][tx << 2];
            ull bb0 = pk2(bv.x, bv.x);
            ull bb1 = pk2(bv.y, bv.y);
            ull bb2 = pk2(bv.z, bv.z);
            ull bb3 = pk2(bv.w, bv.w);
            ffma2(acc2[0][0], a2.x, bb0); ffma2(acc2[1][0], a2.y, bb0);
            ffma2(acc2[0][1], a2.x, bb1); ffma2(acc2[1][1], a2.y, bb1);
            ffma2(acc2[0][2], a2.x, bb2); ffma2(acc2[1][2], a2.y, bb2);
            ffma2(acc2[0][3], a2.x, bb3); ffma2(acc2[1][3], a2.y, bb3);
        }
        __syncthreads();
    }

    float* og = g_Gx + ((size_t)s * G4 + j0) * BB;
#pragma unroll
    for (int j = 0; j < 4; j++) {
        float2 lo = upk2(acc2[0][j]);
        float2 hi = upk2(acc2[1][j]);
        float4 v = make_float4(lo.x, lo.y, hi.x, hi.y);
        *(float4*)&og[(size_t)(tx * 4 + j) * BB + (ty << 2)] = v;
    }
}

// =====================================================================
// Phase 2: persistent recurrence. 128 blocks x 256 threads.
// Block owns 4 h-columns (jh0 = blockIdx.x*4).
// Thread map: b = tid>>2, jhl = tid&3  -> warp = 8 b's x 4 jhl:
//   hv LDS.128 = 8 unique rows = 1 wavefront (128B, banks disjoint via HPAD)
//   w  LDS.128 = 4 unique rows = 1 wavefront (banks disjoint via WPAD)
// Inner loop in packed f32x2 (FFMA2): 8 FFMA2 + 5 LDS per 4 k.
// W_hh double-buffered: next step's rows prefetched during compute.
// =====================================================================
#define HPAD 516                        // 512+4 -> row stride = 4 banks
#define WPAD 516
#define SH_H_FLOATS (BB * HPAD)         // 33024
#define SH_W_FLOATS (2 * 16 * WPAD)     // 16512 (double buffer)
#define SH_ST_FLOATS (BB * 4)           // 256
#define SMEM2_BYTES ((SH_H_FLOATS + SH_W_FLOATS + SH_ST_FLOATS) * 4)  // 199168

__global__ __launch_bounds__(256, 1) void lstm_rec_kernel(
    const float* __restrict__ Whh, float* __restrict__ out) {
    extern __shared__ float smem[];
    float* sh_h  = smem;                              // [64][HPAD]
    float* sh_W  = smem + SH_H_FLOATS;                // 2 x [16][WPAD]
    float* sh_st = sh_W + SH_W_FLOATS;                // [256] h staging

    const int tid = threadIdx.x;
    const int b   = tid >> 2;                         // 0..63
    const int jhl = tid & 3;                          // 0..3
    const int jh0 = blockIdx.x * 4;
    const int jh  = jh0 + jhl;

    float c = 0.f;
    g_h[0][b * HH + jh] = 0.f;                        // zero initial h (block slice)

    // stage W[0] into buffer 0
    {
        const float* wsrc = Whh;
#pragma unroll
        for (int p = 0; p < 8; p++) {
            int fi = p * 256 + tid;                   // 0..2047
            int r  = fi >> 7;                         // local row 0..15
            int kk = (fi & 127) << 2;
            int gate = r >> 2, jl = r & 3;
            float4 v = *(const float4*)(wsrc + (size_t)(gate * HH + jh0 + jl) * HH + kk);
            *(float4*)&sh_W[r * WPAD + kk] = v;
        }
    }
    grid_sync_all();                                  // h + W[0] visible everywhere

    for (int s = 0; s < SS; s++) {
        const int cur = s & 1, nxt = cur ^ 1;
        const float* sWc = sh_W + cur * (16 * WPAD);
        float*       sWn = sh_W + nxt * (16 * WPAD);

        // stage h_prev -> smem (coalesced float4)
        const float* hsrc = g_h[cur];
#pragma unroll
        for (int p = 0; p < 32; p++) {
            int fi = p * 256 + tid;                   // 0..8191
            int hb = fi >> 7;
            int hk = (fi & 127) << 2;
            float4 v = *(const float4*)(hsrc + hb * HH + hk);
            *(float4*)&sh_h[hb * HPAD + hk] = v;
        }

        // prefetch W[s+1] into registers (independent of barrier/compute)
        float4 wreg[8];
        if (s + 1 < SS) {
            const float* wsrc = Whh + (size_t)(s + 1) * G4 * HH;
#pragma unroll
            for (int p = 0; p < 8; p++) {
                int fi = p * 256 + tid;
                int r  = fi >> 7;
                int kk = (fi & 127) << 2;
                int gate = r >> 2, jl = r & 3;
                wreg[p] = *(const float4*)(wsrc + (size_t)(gate * HH + jh0 + jl) * HH + kk);
            }
        }

        // gate bases from precomputed Gx (b contiguous -> coalesced-ish)
        const float* gx = g_Gx + (size_t)s * G4 * BB;
        float a0i = gx[(size_t)(0 * HH + jh) * BB + b];
        float a1i = gx[(size_t)(1 * HH + jh) * BB + b];
        float a2i = gx[(size_t)(2 * HH + jh) * BB + b];
        float a3i = gx[(size_t)(3 * HH + jh) * BB + b];

        __syncthreads();                              // h staged, W[cur] ready

        ull A0 = pk2(a0i, 0.f);
        ull A1 = pk2(a1i, 0.f);
        ull A2 = pk2(a2i, 0.f);
        ull A3 = pk2(a3i, 0.f);

        const float* hrow = &sh_h[b * HPAD];
        const float* w0 = sWc + (0 * 4 + jhl) * WPAD;
        const float* w1 = sWc + (1 * 4 + jhl) * WPAD;
        const float* w2 = sWc + (2 * 4 + jhl) * WPAD;
        const float* w3 = sWc + (3 * 4 + jhl) * WPAD;

#pragma unroll 8
        for (int k = 0; k < HH; k += 4) {
            ulonglong2 h2 = *(const ulonglong2*)(hrow + k);
            ulonglong2 v0 = *(const ulonglong2*)(w0 + k);
            ulonglong2 v1 = *(const ulonglong2*)(w1 + k);
            ulonglong2 v2 = *(const ulonglong2*)(w2 + k);
            ulonglong2 v3 = *(const ulonglong2*)(w3 + k);
            ffma2(A0, h2.x, v0.x); ffma2(A0, h2.y, v0.y);
            ffma2(A1, h2.x, v1.x); ffma2(A1, h2.y, v1.y);
            ffma2(A2, h2.x, v2.x); ffma2(A2, h2.y, v2.y);
            ffma2(A3, h2.x, v3.x); ffma2(A3, h2.y, v3.y);
        }

        float2 u0 = upk2(A0), u1 = upk2(A1), u2 = upk2(A2), u3 = upk2(A3);
        float a0 = u0.x + u0.y;
        float a1 = u1.x + u1.y;
        float a2 = u2.x + u2.y;
        float a3 = u3.x + u3.y;

        float ig = 1.f / (1.f + __expf(-a0));
        float fg = 1.f / (1.f + __expf(-a1));
        float gg = tanhf(a2);
        float og = 1.f / (1.f + __expf(-a3));
        c = fg * c + ig * gg;
        float hval = og * tanhf(c);

        // commit W[s+1] regs -> alternate smem buffer (no sync needed vs cur reads)
        if (s + 1 < SS) {
#pragma unroll
            for (int p = 0; p < 8; p++) {
                int fi = p * 256 + tid;
                int r  = fi >> 7;
                int kk = (fi & 127) << 2;
                *(float4*)&sWn[r * WPAD + kk] = wreg[p];
            }
        }

        sh_st[tid] = hval;                            // sh_st[b*4 + jhl] == sh_st[tid]
        __syncthreads();
        if (tid < 64) {                               // one float4 per batch row
            float4 hv4 = *(float4*)&sh_st[tid * 4];
            *(float4*)&g_h[nxt][tid * HH + jh0] = hv4;
            *(float4*)&out[((size_t)tid * SS + s) * HH + jh0] = hv4;
        }
        grid_sync_all();                              // publish h before next step
    }
}

// ---------------------------------------------------------------------
extern "C" void kernel_launch(void* const* d_in, const int* in_sizes, int n_in,
                              void* d_out, int out_size) {
    const float* x   = (const float*)d_in[0];
    const float* Wih = (const float*)d_in[1];
    const float* Whh = (const float*)d_in[2];
    float* out = (float*)d_out;

    dim3 g1(32, 64);   // 32 j-tiles of 64, 64 timesteps
    gemm_x_kernel<<<g1, 256>>>(x, Wih);

    cudaFuncSetAttribute(lstm_rec_kernel,
                         cudaFuncAttributeMaxDynamicSharedMemorySize, SMEM2_BYTES);
    lstm_rec_kernel<<<NBLK, 256, SMEM2_BYTES>>>(Whh, out);
}

// round 5
// speedup vs baseline: 1.0006x; 1.0006x over previous
#include <cuda_runtime.h>
#include <math.h>

#define BB 64      // batch
#define SS 64      // seq / timesteps
#define IN 512     // input dim
#define HH 512     // hidden dim
#define G4 2048    // 4*H
#define NBLK 128   // persistent blocks for phase 2 (1 CTA/SM, all resident)

typedef unsigned long long ull;

// ---------------- packed fp32x2 helpers (sm_103a FFMA2 path) ----------------
__device__ __forceinline__ void ffma2(ull& d, ull a, ull b) {
    asm("fma.rn.f32x2 %0, %1, %2, %0;" : "+l"(d) : "l"(a), "l"(b));
}
__device__ __forceinline__ ull pk2(float x, float y) {
    ull r; asm("mov.b64 %0, {%1, %2};" : "=l"(r) : "f"(x), "f"(y)); return r;
}
__device__ __forceinline__ float2 upk2(ull v) {
    float2 r; asm("mov.b64 {%0, %1}, %2;" : "=f"(r.x), "=f"(r.y) : "l"(v)); return r;
}

// ---------------- scratch (device globals; no allocation APIs) ----------------
__device__ float g_Gx[(size_t)SS * G4 * BB];   // [s][j][b], 33.5 MB
__device__ float g_h[2][BB * HH];              // double-buffered hidden state
__device__ unsigned int g_bar_cnt = 0;
__device__ volatile unsigned int g_bar_gen = 0;

// ---------------- grid-wide barrier (all NBLK blocks resident) ----------------
__device__ __forceinline__ void grid_sync_all() {
    __syncthreads();
    if (threadIdx.x == 0) {
        unsigned int gen = g_bar_gen;
        __threadfence();
        if (atomicAdd(&g_bar_cnt, 1u) == NBLK - 1) {
            g_bar_cnt = 0;
            __threadfence();
            g_bar_gen = gen + 1;
        } else {
            while (g_bar_gen == gen) { __nanosleep(32); }
        }
        __threadfence();
    }
    __syncthreads();
}

// =====================================================================
// Phase 1: Gx[s][j][b] = sum_k x[b][s][k] * W_ih[s][j][k]
// grid (32 j-tiles, 64 s), 256 threads, 64x64 tile, Ktile=32,
// 4x4 microtile done as 2x4 packed-f32x2 accumulators (FFMA2).
// =====================================================================
__global__ __launch_bounds__(256) void gemm_x_kernel(
    const float* __restrict__ x, const float* __restrict__ Wih) {
    __shared__ float As[32][64];   // [k][b]
    __shared__ float Bs[32][64];   // [k][j]

    const int s   = blockIdx.y;
    const int j0  = blockIdx.x * 64;
    const int tid = threadIdx.x;
    const int ty  = tid >> 4;   // b-group 0..15
    const int tx  = tid & 15;   // j-group 0..15

    const float* xA = x + (size_t)s * IN;
    const float* wB = Wih + ((size_t)s * G4 + j0) * IN;

    ull acc2[2][4];   // acc2[p][j] packs (acc[2p][j], acc[2p+1][j])
#pragma unroll
    for (int p = 0; p < 2; p++)
#pragma unroll
        for (int j = 0; j < 4; j++) acc2[p][j] = 0ull;   // (0.f, 0.f)

    for (int k0 = 0; k0 < IN; k0 += 32) {
#pragma unroll
        for (int p = 0; p < 2; p++) {
            int fi = tid * 2 + p;          // 0..511 float4 index
            int r  = fi >> 3;              // row 0..63
            int kk = (fi & 7) << 2;        // k within chunk
            float4 va = *(const float4*)(xA + (size_t)r * (SS * IN) + k0 + kk);
            As[kk + 0][r] = va.x; As[kk + 1][r] = va.y;
            As[kk + 2][r] = va.z; As[kk + 3][r] = va.w;
            float4 vb = *(const float4*)(wB + (size_t)r * IN + k0 + kk);
            Bs[kk + 0][r] = vb.x; Bs[kk + 1][r] = vb.y;
            Bs[kk + 2][r] = vb.z; Bs[kk + 3][r] = vb.w;
        }
        __syncthreads();
#pragma unroll
        for (int k = 0; k < 32; k++) {
            ulonglong2 a2 = *(const ulonglong2*)&As[k][ty << 2]; // (a0,a1),(a2,a3)
            float4 bv = *(const float4*)&Bs[k][tx << 2];
            ull bb0 = pk2(bv.x, bv.x);
            ull bb1 = pk2(bv.y, bv.y);
            ull bb2 = pk2(bv.z, bv.z);
            ull bb3 = pk2(bv.w, bv.w);
            ffma2(acc2[0][0], a2.x, bb0); ffma2(acc2[1][0], a2.y, bb0);
            ffma2(acc2[0][1], a2.x, bb1); ffma2(acc2[1][1], a2.y, bb1);
            ffma2(acc2[0][2], a2.x, bb2); ffma2(acc2[1][2], a2.y, bb2);
            ffma2(acc2[0][3], a2.x, bb3); ffma2(acc2[1][3], a2.y, bb3);
        }
        __syncthreads();
    }

    float* og = g_Gx + ((size_t)s * G4 + j0) * BB;
#pragma unroll
    for (int j = 0; j < 4; j++) {
        float2 lo = upk2(acc2[0][j]);
        float2 hi = upk2(acc2[1][j]);
        float4 v = make_float4(lo.x, lo.y, hi.x, hi.y);
        *(float4*)&og[(size_t)(tx * 4 + j) * BB + (ty << 2)] = v;
    }
}

// =====================================================================
// Phase 2: persistent recurrence. 128 blocks x 256 threads.
// Block owns 4 h-columns (jh0 = blockIdx.x*4).
// Thread map: b = tid>>2, jhl = tid&3  -> warp = 8 b's x 4 jhl:
//   hv LDS.128 = 8 unique rows = 1 wavefront (128B, banks disjoint via HPAD)
//   w  LDS.128 = 4 unique rows = 1 wavefront (banks disjoint via WPAD)
// Inner loop in packed f32x2 (FFMA2): 8 FFMA2 + 5 LDS per 4 k.
// W_hh double-buffered: next step's rows prefetched during compute.
// =====================================================================
#define HPAD 516                        // 512+4 -> row stride = 4 banks
#define WPAD 516
#define SH_H_FLOATS (BB * HPAD)         // 33024
#define SH_W_FLOATS (2 * 16 * WPAD)     // 16512 (double buffer)
#define SH_ST_FLOATS (BB * 4)           // 256
#define SMEM2_BYTES ((SH_H_FLOATS + SH_W_FLOATS + SH_ST_FLOATS) * 4)  // 199168

__global__ __launch_bounds__(256, 1) void lstm_rec_kernel(
    const float* __restrict__ Whh, float* __restrict__ out) {
    extern __shared__ float smem[];
    float* sh_h  = smem;                              // [64][HPAD]
    float* sh_W  = smem + SH_H_FLOATS;                // 2 x [16][WPAD]
    float* sh_st = sh_W + SH_W_FLOATS;                // [256] h staging

    const int tid = threadIdx.x;
    const int b   = tid >> 2;                         // 0..63
    const int jhl = tid & 3;                          // 0..3
    const int jh0 = blockIdx.x * 4;
    const int jh  = jh0 + jhl;

    float c = 0.f;
    g_h[0][b * HH + jh] = 0.f;                        // zero initial h (block slice)

    // stage W[0] into buffer 0
    {
        const float* wsrc = Whh;
#pragma unroll
        for (int p = 0; p < 8; p++) {
            int fi = p * 256 + tid;                   // 0..2047
            int r  = fi >> 7;                         // local row 0..15
            int kk = (fi & 127) << 2;
            int gate = r >> 2, jl = r & 3;
            float4 v = *(const float4*)(wsrc + (size_t)(gate * HH + jh0 + jl) * HH + kk);
            *(float4*)&sh_W[r * WPAD + kk] = v;
        }
    }
    grid_sync_all();                                  // h + W[0] visible everywhere

    for (int s = 0; s < SS; s++) {
        const int cur = s & 1, nxt = cur ^ 1;
        const float* sWc = sh_W + cur * (16 * WPAD);
        float*       sWn = sh_W + nxt * (16 * WPAD);

        // stage h_prev -> smem (coalesced float4)
        const float* hsrc = g_h[cur];
#pragma unroll
        for (int p = 0; p < 32; p++) {
            int fi = p * 256 + tid;                   // 0..8191
            int hb = fi >> 7;
            int hk = (fi & 127) << 2;
            float4 v = *(const float4*)(hsrc + hb * HH + hk);
            *(float4*)&sh_h[hb * HPAD + hk] = v;
        }

        // prefetch W[s+1] into registers (independent of barrier/compute)
        float4 wreg[8];
        if (s + 1 < SS) {
            const float* wsrc = Whh + (size_t)(s + 1) * G4 * HH;
#pragma unroll
            for (int p = 0; p < 8; p++) {
                int fi = p * 256 + tid;
                int r  = fi >> 7;
                int kk = (fi & 127) << 2;
                int gate = r >> 2, jl = r & 3;
                wreg[p] = *(const float4*)(wsrc + (size_t)(gate * HH + jh0 + jl) * HH + kk);
            }
        }

        // gate bases from precomputed Gx (b contiguous -> coalesced-ish)
        const float* gx = g_Gx + (size_t)s * G4 * BB;
        float a0i = gx[(size_t)(0 * HH + jh) * BB + b];
        float a1i = gx[(size_t)(1 * HH + jh) * BB + b];
        float a2i = gx[(size_t)(2 * HH + jh) * BB + b];
        float a3i = gx[(size_t)(3 * HH + jh) * BB + b];

        __syncthreads();                              // h staged, W[cur] ready

        ull A0 = pk2(a0i, 0.f);
        ull A1 = pk2(a1i, 0.f);
        ull A2 = pk2(a2i, 0.f);
        ull A3 = pk2(a3i, 0.f);

        const float* hrow = &sh_h[b * HPAD];
        const float* w0 = sWc + (0 * 4 + jhl) * WPAD;
        const float* w1 = sWc + (1 * 4 + jhl) * WPAD;
        const float* w2 = sWc + (2 * 4 + jhl) * WPAD;
        const float* w3 = sWc + (3 * 4 + jhl) * WPAD;

#pragma unroll 8
        for (int k = 0; k < HH; k += 4) {
            ulonglong2 h2 = *(const ulonglong2*)(hrow + k);
            ulonglong2 v0 = *(const ulonglong2*)(w0 + k);
            ulonglong2 v1 = *(const ulonglong2*)(w1 + k);
            ulonglong2 v2 = *(const ulonglong2*)(w2 + k);
            ulonglong2 v3 = *(const ulonglong2*)(w3 + k);
            ffma2(A0, h2.x, v0.x); ffma2(A0, h2.y, v0.y);
            ffma2(A1, h2.x, v1.x); ffma2(A1, h2.y, v1.y);
            ffma2(A2, h2.x, v2.x); ffma2(A2, h2.y, v2.y);
            ffma2(A3, h2.x, v3.x); ffma2(A3, h2.y, v3.y);
        }

        float2 u0 = upk2(A0), u1 = upk2(A1), u2 = upk2(A2), u3 = upk2(A3);
        float a0 = u0.x + u0.y;
        float a1 = u1.x + u1.y;
        float a2 = u2.x + u2.y;
        float a3 = u3.x + u3.y;

        float ig = 1.f / (1.f + __expf(-a0));
        float fg = 1.f / (1.f + __expf(-a1));
        float gg = tanhf(a2);
        float og = 1.f / (1.f + __expf(-a3));
        c = fg * c + ig * gg;
        float hval = og * tanhf(c);

        // commit W[s+1] regs -> alternate smem buffer (no sync needed vs cur reads)
        if (s + 1 < SS) {
#pragma unroll
            for (int p = 0; p < 8; p++) {
                int fi = p * 256 + tid;
                int r  = fi >> 7;
                int kk = (fi & 127) << 2;
                *(float4*)&sWn[r * WPAD + kk] = wreg[p];
            }
        }

        sh_st[tid] = hval;                            // sh_st[b*4 + jhl] == sh_st[tid]
        __syncthreads();
        if (tid < 64) {                               // one float4 per batch row
            float4 hv4 = *(float4*)&sh_st[tid * 4];
            *(float4*)&g_h[nxt][tid * HH + jh0] = hv4;
            *(float4*)&out[((size_t)tid * SS + s) * HH + jh0] = hv4;
        }
        grid_sync_all();                              // publish h before next step
    }
}

// ---------------------------------------------------------------------
extern "C" void kernel_launch(void* const* d_in, const int* in_sizes, int n_in,
                              void* d_out, int out_size) {
    const float* x   = (const float*)d_in[0];
    const float* Wih = (const float*)d_in[1];
    const float* Whh = (const float*)d_in[2];
    float* out = (float*)d_out;

    dim3 g1(32, 64);   // 32 j-tiles of 64, 64 timesteps
    gemm_x_kernel<<<g1, 256>>>(x, Wih);

    cudaFuncSetAttribute(lstm_rec_kernel,
                         cudaFuncAttributeMaxDynamicSharedMemorySize, SMEM2_BYTES);
    lstm_rec_kernel<<<NBLK, 256, SMEM2_BYTES>>>(Whh, out);
}

// round 12
// speedup vs baseline: 1.2565x; 1.2558x over previous
#include <cuda_runtime.h>
#include <math.h>
#include <stdint.h>

#define BB 64      // batch
#define SS 64      // seq
#define IND 512    // input dim
#define HH 512     // hidden dim
#define G4 2048    // 4*H
#define NBLK 128   // persistent CTAs, phase 2

typedef unsigned long long ull;

// ---------------- packed fp32x2 (FFMA2) ----------------
__device__ __forceinline__ void ffma2(ull& d, ull a, ull b) {
    asm("fma.rn.f32x2 %0, %1, %2, %0;" : "+l"(d) : "l"(a), "l"(b));
}
__device__ __forceinline__ float2 upk2(ull v) {
    float2 r; asm("mov.b64 {%0, %1}, %2;" : "=f"(r.x), "=f"(r.y) : "l"(v)); return r;
}

// ---------------- cp.async ----------------
__device__ __forceinline__ uint32_t smem_u32(const void* p) {
    uint32_t a;
    asm("{ .reg .u64 t; cvta.to.shared.u64 t, %1; cvt.u32.u64 %0, t; }" : "=r"(a) : "l"(p));
    return a;
}
__device__ __forceinline__ void cp16(uint32_t dst, const void* src) {
    uint64_t g; asm("cvta.to.global.u64 %0, %1;" : "=l"(g) : "l"(src));
    asm volatile("cp.async.cg.shared.global [%0], [%1], 16;" :: "r"(dst), "l"(g) : "memory");
}
#define CP_COMMIT() asm volatile("cp.async.commit_group;" ::: "memory")
#define CP_WAIT(n)  asm volatile("cp.async.wait_group %0;" :: "n"(n) : "memory")

// ---------------- device scratch ----------------
__device__ float g_Gx[(size_t)SS * G4 * BB];   // [s][row=gate*512+col][b]
__device__ float g_h[2][BB * HH];
__device__ unsigned int g_bar_cnt = 0;
__device__ volatile unsigned int g_bar_gen = 0;

__device__ __forceinline__ void grid_sync_all() {
    __syncthreads();
    if (threadIdx.x == 0) {
        unsigned int gen = g_bar_gen;
        __threadfence();
        if (atomicAdd(&g_bar_cnt, 1u) == NBLK - 1) {
            g_bar_cnt = 0;
            __threadfence();
            g_bar_gen = gen + 1;
        } else {
            while (g_bar_gen == gen) { __nanosleep(32); }
        }
        __threadfence();
    }
    __syncthreads();
}

__device__ __forceinline__ float sigf(float x) { return 1.f / (1.f + __expf(-x)); }

// =====================================================================
// Phase 1: Gx[s][row][b] = sum_k Wih[s][row][k] * x[b][s][k]
// grid (16 row-tiles, 64 s), 128 threads, CTA tile 128 rows x 64 b,
// 8x8 microtile, cp.async double-buffered 64-k chunks.
// =====================================================================
#define AROW 68                         // 64 + 4 pad
#define P1_BUF ((64 + 128) * AROW)      // floats per buffer = 13056
#define P1_SMEM (2 * P1_BUF * 4)        // 104448 B

__global__ __launch_bounds__(128, 1) void gemm_x_kernel(
    const float* __restrict__ x, const float* __restrict__ Wih) {
    extern __shared__ float sm[];
    const int tid = threadIdx.x;
    const int tb = tid & 7, tr = tid >> 3;
    const int jt = blockIdx.x, s = blockIdx.y;

    ull acc[8][8];
#pragma unroll
    for (int i = 0; i < 8; i++)
#pragma unroll
        for (int j = 0; j < 8; j++) acc[i][j] = 0ull;

    // stage chunk 0
    {
        float* base = sm;
#pragma unroll
        for (int p = 0; p < 8; p++) {
            int fi = tid + 128 * p, b = fi >> 4, f = fi & 15;
            cp16(smem_u32(base + b * AROW + f * 4),
                 x + ((size_t)b * SS + s) * IND + f * 4);
        }
#pragma unroll
        for (int p = 0; p < 16; p++) {
            int fi = tid + 128 * p, r = fi >> 4, f = fi & 15;
            cp16(smem_u32(base + 64 * AROW + r * AROW + f * 4),
                 Wih + ((size_t)s * G4 + jt * 128 + r) * IND + f * 4);
        }
        CP_COMMIT();
    }

    for (int c = 0; c < 8; c++) {
        CP_WAIT(0);
        __syncthreads();
        if (c + 1 < 8) {
            float* base = sm + ((c + 1) & 1) * P1_BUF;
            int k0 = (c + 1) * 64;
#pragma unroll
            for (int p = 0; p < 8; p++) {
                int fi = tid + 128 * p, b = fi >> 4, f = fi & 15;
                cp16(smem_u32(base + b * AROW + f * 4),
                     x + ((size_t)b * SS + s) * IND + k0 + f * 4);
            }
#pragma unroll
            for (int p = 0; p < 16; p++) {
                int fi = tid + 128 * p, r = fi >> 4, f = fi & 15;
                cp16(smem_u32(base + 64 * AROW + r * AROW + f * 4),
                     Wih + ((size_t)s * G4 + jt * 128 + r) * IND + k0 + f * 4);
            }
            CP_COMMIT();
        } else {
            CP_COMMIT();
        }

        const float* ab = sm + (c & 1) * P1_BUF + tb * AROW;
        const float* wb = sm + (c & 1) * P1_BUF + 64 * AROW + tr * AROW;
#pragma unroll 2
        for (int q = 0; q < 16; q++) {
            const int o = q * 4;
            ulonglong2 a2[8];
#pragma unroll
            for (int bb = 0; bb < 8; bb++)
                a2[bb] = *(const ulonglong2*)(ab + bb * (8 * AROW) + o);
#pragma unroll
            for (int rr = 0; rr < 8; rr++) {
                ulonglong2 w2 = *(const ulonglong2*)(wb + rr * (16 * AROW) + o);
#pragma unroll
                for (int bb = 0; bb < 8; bb++) {
                    ffma2(acc[bb][rr], a2[bb].x, w2.x);
                    ffma2(acc[bb][rr], a2[bb].y, w2.y);
                }
            }
        }
        __syncthreads();
    }

#pragma unroll
    for (int rr = 0; rr < 8; rr++) {
        int row = jt * 128 + tr + 16 * rr;
        float* dst = g_Gx + ((size_t)s * G4 + row) * BB + tb;
#pragma unroll
        for (int bb = 0; bb < 8; bb++) {
            float2 u = upk2(acc[bb][rr]);
            dst[8 * bb] = u.x + u.y;
        }
    }
}

// =====================================================================
// Phase 2: persistent recurrence, 128 CTAs x 256 threads.
// CTA owns 4 h-cols (jh0 = blockIdx.x*4). warp = 8-batch group.
// lane = ks*4 + j: ks splits K=512 into 8 x 64-k slices, j = column.
// k-block m stored at row*HROW + 68*m + (k&63)  [cumulative 4-float skew,
// DISJOINT blocks — this fixes the R11 overlap bug]. HROW = 552 (≡8 mod 32):
//   W LDS.128: lanes hit banks 8j+4ks mod 32 -> all 32 once, conflict-free.
//   h LDS.128: 8 distinct chunks broadcast x4 -> 1 wavefront.
// shfl.bfly reduce over ks; ks==0 lanes store; c[8] in registers.
// =====================================================================
#define HROW 552                        // 8*64 + 8*skew..., 552 % 32 == 8, 16B stride
#define SH_H (BB * HROW)                // 35328 floats
#define WBUF (16 * HROW)                // 8832 floats
#define P2_SMEM ((SH_H + 2 * WBUF) * 4) // 211968 B

__global__ __launch_bounds__(256, 1) void lstm_rec_kernel(
    const float* __restrict__ Whh, float* __restrict__ out) {
    extern __shared__ float sm[];
    float* sh_h = sm;                  // [64][HROW]
    float* sh_W = sm + SH_H;           // 2 x [16][HROW]

    const int tid = threadIdx.x;
    const int w   = tid >> 5;
    const int lane = tid & 31;
    const int j   = lane & 3;
    const int ks  = lane >> 2;
    const int jh0 = blockIdx.x * 4;
    const int kofs = 68 * ks;           // disjoint skewed k-base

    g_h[0][blockIdx.x * 256 + tid] = 0.f;

    // stage W[0] -> buffer 0   (smem float offset = kf + 4*(kf>>6))
#pragma unroll
    for (int p = 0; p < 8; p++) {
        int fi = p * 256 + tid;
        int r = fi >> 7, kf = (fi & 127) * 4;
        int grow = (r >> 2) * 512 + jh0 + (r & 3);
        cp16(smem_u32(sh_W + r * HROW + kf + ((kf >> 6) << 2)),
             Whh + (size_t)grow * HH + kf);
    }
    CP_COMMIT();

    float c[8];
#pragma unroll
    for (int u = 0; u < 8; u++) c[u] = 0.f;

    grid_sync_all();

    for (int s = 0; s < SS; s++) {
        const int cur = s & 1, nxt = cur ^ 1;

        // stage h_prev (group A)
        const float* hsrc = g_h[cur];
#pragma unroll
        for (int p = 0; p < 32; p++) {
            int fi = p * 256 + tid;
            int hb = fi >> 7, kf = (fi & 127) * 4;
            cp16(smem_u32(sh_h + hb * HROW + kf + ((kf >> 6) << 2)),
                 hsrc + hb * HH + kf);
        }
        CP_COMMIT();

        // prefetch W[s+1] -> other buffer (group B, may stay in flight)
        if (s + 1 < SS) {
            const float* wsrc = Whh + (size_t)(s + 1) * G4 * HH;
            float* wdst = sh_W + nxt * WBUF;
#pragma unroll
            for (int p = 0; p < 8; p++) {
                int fi = p * 256 + tid;
                int r = fi >> 7, kf = (fi & 127) * 4;
                int grow = (r >> 2) * 512 + jh0 + (r & 3);
                cp16(smem_u32(wdst + r * HROW + kf + ((kf >> 6) << 2)),
                     wsrc + (size_t)grow * HH + kf);
            }
        }
        CP_COMMIT();

        CP_WAIT(1);                    // h + this step's W arrived; next W may fly
        __syncthreads();

        // ---- GEMM slice: acc[8b][4g] over this lane's 64 k ----
        ull acc[8][4];
#pragma unroll
        for (int bb = 0; bb < 8; bb++)
#pragma unroll
            for (int g = 0; g < 4; g++) acc[bb][g] = 0ull;

        const float* hb = sh_h + (w * 8) * HROW + kofs;
        const float* wb = sh_W + cur * WBUF + j * HROW + kofs;

#pragma unroll 4
        for (int q = 0; q < 16; q++) {
            const int o = q * 4;
            ulonglong2 w0 = *(const ulonglong2*)(wb + o);
            ulonglong2 w1 = *(const ulonglong2*)(wb + 4 * HROW + o);
            ulonglong2 w2 = *(const ulonglong2*)(wb + 8 * HROW + o);
            ulonglong2 w3 = *(const ulonglong2*)(wb + 12 * HROW + o);
#pragma unroll
            for (int bb = 0; bb < 8; bb++) {
                ulonglong2 h2 = *(const ulonglong2*)(hb + bb * HROW + o);
                ffma2(acc[bb][0], h2.x, w0.x); ffma2(acc[bb][0], h2.y, w0.y);
                ffma2(acc[bb][1], h2.x, w1.x); ffma2(acc[bb][1], h2.y, w1.y);
                ffma2(acc[bb][2], h2.x, w2.x); ffma2(acc[bb][2], h2.y, w2.y);
                ffma2(acc[bb][3], h2.x, w3.x); ffma2(acc[bb][3], h2.y, w3.y);
            }
        }

        // ---- reduce over ks (lane bits 2..4) ----
        float r[8][4];
#pragma unroll
        for (int bb = 0; bb < 8; bb++)
#pragma unroll
            for (int g = 0; g < 4; g++) {
                float2 u = upk2(acc[bb][g]);
                r[bb][g] = u.x + u.y;
            }
#pragma unroll
        for (int m = 4; m <= 16; m <<= 1)
#pragma unroll
            for (int bb = 0; bb < 8; bb++)
#pragma unroll
                for (int g = 0; g < 4; g++)
                    r[bb][g] += __shfl_xor_sync(0xffffffffu, r[bb][g], m);

        // ---- cell update (redundant across ks; ks==0 stores) ----
        const float* gx = g_Gx + (size_t)s * G4 * BB;
        float gxa[4][8];
#pragma unroll
        for (int g = 0; g < 4; g++) {
            const float* p = gx + (size_t)(g * 512 + jh0 + j) * BB + 8 * w;
            float4 lo = *(const float4*)(p);
            float4 hi = *(const float4*)(p + 4);
            gxa[g][0] = lo.x; gxa[g][1] = lo.y; gxa[g][2] = lo.z; gxa[g][3] = lo.w;
            gxa[g][4] = hi.x; gxa[g][5] = hi.y; gxa[g][6] = hi.z; gxa[g][7] = hi.w;
        }
#pragma unroll
        for (int bb = 0; bb < 8; bb++) {
            float a0 = r[bb][0] + gxa[0][bb];
            float a1 = r[bb][1] + gxa[1][bb];
            float a2 = r[bb][2] + gxa[2][bb];
            float a3 = r[bb][3] + gxa[3][bb];
            float ig = sigf(a0);
            float fg = sigf(a1);
            float gg = tanhf(a2);
            float og = sigf(a3);
            c[bb] = fg * c[bb] + ig * gg;
            float hv = og * tanhf(c[bb]);
            if (ks == 0) {
                int b = 8 * w + bb;
                g_h[nxt][b * HH + jh0 + j] = hv;
                out[((size_t)b * SS + s) * HH + jh0 + j] = hv;
            }
        }
        grid_sync_all();
    }
}

// ---------------------------------------------------------------------
extern "C" void kernel_launch(void* const* d_in, const int* in_sizes, int n_in,
                              void* d_out, int out_size) {
    const float* x   = (const float*)d_in[0];
    const float* Wih = (const float*)d_in[1];
    const float* Whh = (const float*)d_in[2];
    float* out = (float*)d_out;

    cudaFuncSetAttribute(gemm_x_kernel,
                         cudaFuncAttributeMaxDynamicSharedMemorySize, P1_SMEM);
    cudaFuncSetAttribute(lstm_rec_kernel,
                         cudaFuncAttributeMaxDynamicSharedMemorySize, P2_SMEM);

    dim3 g1(16, 64);
    gemm_x_kernel<<<g1, 128, P1_SMEM>>>(x, Wih);
    lstm_rec_kernel<<<NBLK, 256, P2_SMEM>>>(Whh, out);
}

// round 13
// speedup vs baseline: 1.4064x; 1.1193x over previous
#include <cuda_runtime.h>
#include <math.h>
#include <stdint.h>

#define BB 64      // batch
#define SS 64      // seq
#define IND 512    // input dim
#define HH 512     // hidden dim
#define G4 2048    // 4*H
#define NBLK 128   // persistent CTAs, phase 2

typedef unsigned long long ull;

// ---------------- packed fp32x2 (FFMA2) ----------------
__device__ __forceinline__ void ffma2(ull& d, ull a, ull b) {
    asm("fma.rn.f32x2 %0, %1, %2, %0;" : "+l"(d) : "l"(a), "l"(b));
}
__device__ __forceinline__ float2 upk2(ull v) {
    float2 r; asm("mov.b64 {%0, %1}, %2;" : "=f"(r.x), "=f"(r.y) : "l"(v)); return r;
}

// ---------------- cp.async ----------------
__device__ __forceinline__ uint32_t smem_u32(const void* p) {
    uint32_t a;
    asm("{ .reg .u64 t; cvta.to.shared.u64 t, %1; cvt.u32.u64 %0, t; }" : "=r"(a) : "l"(p));
    return a;
}
__device__ __forceinline__ void cp16(uint32_t dst, const void* src) {
    uint64_t g; asm("cvta.to.global.u64 %0, %1;" : "=l"(g) : "l"(src));
    asm volatile("cp.async.cg.shared.global [%0], [%1], 16;" :: "r"(dst), "l"(g) : "memory");
}
#define CP_COMMIT() asm volatile("cp.async.commit_group;" ::: "memory")
#define CP_WAIT(n)  asm volatile("cp.async.wait_group %0;" :: "n"(n) : "memory")

// ---------------- device scratch ----------------
__device__ float g_Gx[(size_t)SS * G4 * BB];   // [s][row=gate*512+col][b]
__device__ float g_h[2][BB * HH];
__device__ unsigned int g_arrive;              // monotonic barrier counter (reset by phase 1)

// light grid barrier: release-atomic arrive + acquire-poll, NO membar.gl (no L1 flush)
__device__ __forceinline__ void grid_sync_step(unsigned int target) {
    __syncthreads();
    if (threadIdx.x == 0) {
        unsigned int old, v;
        asm volatile("atom.release.gpu.add.u32 %0, [%1], 1;"
                     : "=r"(old) : "l"(&g_arrive) : "memory");
        do {
            asm volatile("ld.acquire.gpu.u32 %0, [%1];"
                         : "=r"(v) : "l"(&g_arrive) : "memory");
        } while (v < target);
    }
    __syncthreads();
}

__device__ __forceinline__ float sigf(float x) { return 1.f / (1.f + __expf(-x)); }

// =====================================================================
// Phase 1: Gx[s][row][b] = sum_k Wih[s][row][k] * x[b][s][k]
// grid (16 row-tiles, 64 s), 128 threads, 8x8 microtile, cp.async dbuf.
// Also resets the phase-2 barrier counter (kernels serialize on stream).
// =====================================================================
#define AROW 68
#define P1_BUF ((64 + 128) * AROW)
#define P1_SMEM (2 * P1_BUF * 4)

__global__ __launch_bounds__(128, 1) void gemm_x_kernel(
    const float* __restrict__ x, const float* __restrict__ Wih) {
    extern __shared__ float sm[];
    const int tid = threadIdx.x;
    const int tb = tid & 7, tr = tid >> 3;
    const int jt = blockIdx.x, s = blockIdx.y;

    if (jt == 0 && s == 0 && tid == 0) g_arrive = 0;   // reset phase-2 barrier

    ull acc[8][8];
#pragma unroll
    for (int i = 0; i < 8; i++)
#pragma unroll
        for (int j = 0; j < 8; j++) acc[i][j] = 0ull;

    {
        float* base = sm;
#pragma unroll 4
        for (int p = 0; p < 8; p++) {
            int fi = tid + 128 * p, b = fi >> 4, f = fi & 15;
            cp16(smem_u32(base + b * AROW + f * 4),
                 x + ((size_t)b * SS + s) * IND + f * 4);
        }
#pragma unroll 4
        for (int p = 0; p < 16; p++) {
            int fi = tid + 128 * p, r = fi >> 4, f = fi & 15;
            cp16(smem_u32(base + 64 * AROW + r * AROW + f * 4),
                 Wih + ((size_t)s * G4 + jt * 128 + r) * IND + f * 4);
        }
        CP_COMMIT();
    }

    for (int c = 0; c < 8; c++) {
        CP_WAIT(0);
        __syncthreads();
        if (c + 1 < 8) {
            float* base = sm + ((c + 1) & 1) * P1_BUF;
            int k0 = (c + 1) * 64;
#pragma unroll 4
            for (int p = 0; p < 8; p++) {
                int fi = tid + 128 * p, b = fi >> 4, f = fi & 15;
                cp16(smem_u32(base + b * AROW + f * 4),
                     x + ((size_t)b * SS + s) * IND + k0 + f * 4);
            }
#pragma unroll 4
            for (int p = 0; p < 16; p++) {
                int fi = tid + 128 * p, r = fi >> 4, f = fi & 15;
                cp16(smem_u32(base + 64 * AROW + r * AROW + f * 4),
                     Wih + ((size_t)s * G4 + jt * 128 + r) * IND + k0 + f * 4);
            }
            CP_COMMIT();
        } else {
            CP_COMMIT();
        }

        const float* ab = sm + (c & 1) * P1_BUF + tb * AROW;
        const float* wb = sm + (c & 1) * P1_BUF + 64 * AROW + tr * AROW;
#pragma unroll 2
        for (int q = 0; q < 16; q++) {
            const int o = q * 4;
            ulonglong2 a2[8];
#pragma unroll
            for (int bb = 0; bb < 8; bb++)
                a2[bb] = *(const ulonglong2*)(ab + bb * (8 * AROW) + o);
#pragma unroll
            for (int rr = 0; rr < 8; rr++) {
                ulonglong2 w2 = *(const ulonglong2*)(wb + rr * (16 * AROW) + o);
#pragma unroll
                for (int bb = 0; bb < 8; bb++) {
                    ffma2(acc[bb][rr], a2[bb].x, w2.x);
                    ffma2(acc[bb][rr], a2[bb].y, w2.y);
                }
            }
        }
        __syncthreads();
    }

#pragma unroll
    for (int rr = 0; rr < 8; rr++) {
        int row = jt * 128 + tr + 16 * rr;
        float* dst = g_Gx + ((size_t)s * G4 + row) * BB + tb;
#pragma unroll
        for (int bb = 0; bb < 8; bb++) {
            float2 u = upk2(acc[bb][rr]);
            dst[8 * bb] = u.x + u.y;
        }
    }
}

// =====================================================================
// Phase 2: persistent recurrence, 128 CTAs x 256 threads.
// CTA owns 4 h-cols. warp = 8-batch group; lane = ks*4+j (8-way k-split).
// k-block m at row*HROW + 68*m (disjoint skew), HROW=552 -> conflict-free.
// Epilogue only on ks==0 lanes (8x less MUFU/LDG, lower reg pressure).
// =====================================================================
#define HROW 552
#define SH_H (BB * HROW)
#define WBUF (16 * HROW)
#define P2_SMEM ((SH_H + 2 * WBUF) * 4)

__global__ __launch_bounds__(256, 1) void lstm_rec_kernel(
    const float* __restrict__ Whh, float* __restrict__ out) {
    extern __shared__ float sm[];
    float* sh_h = sm;                  // [64][HROW]
    float* sh_W = sm + SH_H;           // 2 x [16][HROW]

    const int tid = threadIdx.x;
    const int w   = tid >> 5;
    const int lane = tid & 31;
    const int j   = lane & 3;
    const int ks  = lane >> 2;
    const int jh0 = blockIdx.x * 4;
    const int kofs = 68 * ks;

    g_h[0][blockIdx.x * 256 + tid] = 0.f;

    // stage W[0] -> buffer 0
#pragma unroll 2
    for (int p = 0; p < 8; p++) {
        int fi = p * 256 + tid;
        int r = fi >> 7, kf = (fi & 127) * 4;
        int grow = (r >> 2) * 512 + jh0 + (r & 3);
        cp16(smem_u32(sh_W + r * HROW + kf + ((kf >> 6) << 2)),
             Whh + (size_t)grow * HH + kf);
    }
    CP_COMMIT();

    float c[8];
#pragma unroll
    for (int u = 0; u < 8; u++) c[u] = 0.f;

    unsigned int target = NBLK;
    grid_sync_step(target);

    for (int s = 0; s < SS; s++) {
        const int cur = s & 1, nxt = cur ^ 1;

        // stage h_prev (group A)
        const float* hsrc = g_h[cur];
#pragma unroll 4
        for (int p = 0; p < 32; p++) {
            int fi = p * 256 + tid;
            int hb = fi >> 7, kf = (fi & 127) * 4;
            cp16(smem_u32(sh_h + hb * HROW + kf + ((kf >> 6) << 2)),
                 hsrc + hb * HH + kf);
        }
        CP_COMMIT();

        // prefetch W[s+1] -> other buffer (group B, may stay in flight)
        if (s + 1 < SS) {
            const float* wsrc = Whh + (size_t)(s + 1) * G4 * HH;
            float* wdst = sh_W + nxt * WBUF;
#pragma unroll 2
            for (int p = 0; p < 8; p++) {
                int fi = p * 256 + tid;
                int r = fi >> 7, kf = (fi & 127) * 4;
                int grow = (r >> 2) * 512 + jh0 + (r & 3);
                cp16(smem_u32(wdst + r * HROW + kf + ((kf >> 6) << 2)),
                     wsrc + (size_t)grow * HH + kf);
            }
        }
        CP_COMMIT();

        CP_WAIT(1);                    // h + this step's W arrived
        __syncthreads();

        // ---- GEMM slice: acc[8b][4g] over this lane's 64 k ----
        ull acc[8][4];
#pragma unroll
        for (int bb = 0; bb < 8; bb++)
#pragma unroll
            for (int g = 0; g < 4; g++) acc[bb][g] = 0ull;

        const float* hb = sh_h + (w * 8) * HROW + kofs;
        const float* wb = sh_W + cur * WBUF + j * HROW + kofs;

#pragma unroll 4
        for (int q = 0; q < 16; q++) {
            const int o = q * 4;
            ulonglong2 w0 = *(const ulonglong2*)(wb + o);
            ulonglong2 w1 = *(const ulonglong2*)(wb + 4 * HROW + o);
            ulonglong2 w2 = *(const ulonglong2*)(wb + 8 * HROW + o);
            ulonglong2 w3 = *(const ulonglong2*)(wb + 12 * HROW + o);
#pragma unroll
            for (int bb = 0; bb < 8; bb++) {
                ulonglong2 h2 = *(const ulonglong2*)(hb + bb * HROW + o);
                ffma2(acc[bb][0], h2.x, w0.x); ffma2(acc[bb][0], h2.y, w0.y);
                ffma2(acc[bb][1], h2.x, w1.x); ffma2(acc[bb][1], h2.y, w1.y);
                ffma2(acc[bb][2], h2.x, w2.x); ffma2(acc[bb][2], h2.y, w2.y);
                ffma2(acc[bb][3], h2.x, w3.x); ffma2(acc[bb][3], h2.y, w3.y);
            }
        }

        // unpack
        float r[8][4];
#pragma unroll
        for (int bb = 0; bb < 8; bb++)
#pragma unroll
            for (int g = 0; g < 4; g++) {
                float2 u = upk2(acc[bb][g]);
                r[bb][g] = u.x + u.y;
            }

        // Gx prefetch for ks==0 lanes only (latency overlaps the shfl reduce)
        float gxa[4][8];
        if (ks == 0) {
            const float* gx = g_Gx + (size_t)s * G4 * BB;
#pragma unroll
            for (int g = 0; g < 4; g++) {
                const float* p = gx + (size_t)(g * 512 + jh0 + j) * BB + 8 * w;
                float4 lo = *(const float4*)(p);
                float4 hi = *(const float4*)(p + 4);
                gxa[g][0] = lo.x; gxa[g][1] = lo.y; gxa[g][2] = lo.z; gxa[g][3] = lo.w;
                gxa[g][4] = hi.x; gxa[g][5] = hi.y; gxa[g][6] = hi.z; gxa[g][7] = hi.w;
            }
        }

        // reduce over ks (all lanes participate)
#pragma unroll
        for (int m = 4; m <= 16; m <<= 1)
#pragma unroll
            for (int bb = 0; bb < 8; bb++)
#pragma unroll
                for (int g = 0; g < 4; g++)
                    r[bb][g] += __shfl_xor_sync(0xffffffffu, r[bb][g], m);

        // cell update + stores: ks==0 lanes only
        if (ks == 0) {
#pragma unroll
            for (int bb = 0; bb < 8; bb++) {
                float a0 = r[bb][0] + gxa[0][bb];
                float a1 = r[bb][1] + gxa[1][bb];
                float a2 = r[bb][2] + gxa[2][bb];
                float a3 = r[bb][3] + gxa[3][bb];
                float ig = sigf(a0);
                float fg = sigf(a1);
                float gg = tanhf(a2);
                float og = sigf(a3);
                c[bb] = fg * c[bb] + ig * gg;
                float hv = og * tanhf(c[bb]);
                int b = 8 * w + bb;
                g_h[nxt][b * HH + jh0 + j] = hv;
                out[((size_t)b * SS + s) * HH + jh0 + j] = hv;
            }
        }
        target += NBLK;
        grid_sync_step(target);
    }
}

// ---------------------------------------------------------------------
extern "C" void kernel_launch(void* const* d_in, const int* in_sizes, int n_in,
                              void* d_out, int out_size) {
    const float* x   = (const float*)d_in[0];
    const float* Wih = (const float*)d_in[1];
    const float* Whh = (const float*)d_in[2];
    float* out = (float*)d_out;

    cudaFuncSetAttribute(gemm_x_kernel,
                         cudaFuncAttributeMaxDynamicSharedMemorySize, P1_SMEM);
    cudaFuncSetAttribute(lstm_rec_kernel,
                         cudaFuncAttributeMaxDynamicSharedMemorySize, P2_SMEM);

    dim3 g1(16, 64);
    gemm_x_kernel<<<g1, 128, P1_SMEM>>>(x, Wih);
    lstm_rec_kernel<<<NBLK, 256, P2_SMEM>>>(Whh, out);
}

// round 14
// speedup vs baseline: 1.6118x; 1.1461x over previous
#include <cuda_runtime.h>
#include <math.h>
#include <stdint.h>

#define BB 64      // batch
#define SS 64      // seq
#define IND 512    // input dim
#define HH 512     // hidden dim
#define G4 2048    // 4*H
#define NBLK 128   // persistent CTAs, phase 2

typedef unsigned long long ull;

// ---------------- packed fp32x2 (FFMA2) ----------------
__device__ __forceinline__ void ffma2(ull& d, ull a, ull b) {
    asm("fma.rn.f32x2 %0, %1, %2, %0;" : "+l"(d) : "l"(a), "l"(b));
}
__device__ __forceinline__ float2 upk2(ull v) {
    float2 r; asm("mov.b64 {%0, %1}, %2;" : "=f"(r.x), "=f"(r.y) : "l"(v)); return r;
}

// ---------------- cp.async ----------------
__device__ __forceinline__ uint32_t smem_u32(const void* p) {
    uint32_t a;
    asm("{ .reg .u64 t; cvta.to.shared.u64 t, %1; cvt.u32.u64 %0, t; }" : "=r"(a) : "l"(p));
    return a;
}
__device__ __forceinline__ void cp16(uint32_t dst, const void* src) {
    uint64_t g; asm("cvta.to.global.u64 %0, %1;" : "=l"(g) : "l"(src));
    asm volatile("cp.async.cg.shared.global [%0], [%1], 16;" :: "r"(dst), "l"(g) : "memory");
}
#define CP_COMMIT() asm volatile("cp.async.commit_group;" ::: "memory")
#define CP_WAIT(n)  asm volatile("cp.async.wait_group %0;" :: "n"(n) : "memory")

// ---------------- device scratch ----------------
__device__ float g_Gx[(size_t)SS * G4 * BB];   // [s][row=gate*512+col][b]
__device__ float g_h[2][BB * HH];
__device__ unsigned int g_arrive;              // monotonic barrier counter (reset by phase 1)

// grid barrier: no-return red.release arrive + acquire poll (no L1 flush, no RT wait)
__device__ __forceinline__ void grid_sync_step(unsigned int target) {
    __syncthreads();
    if (threadIdx.x == 0) {
        asm volatile("red.release.gpu.add.u32 [%0], 1;" :: "l"(&g_arrive) : "memory");
        unsigned int v;
        do {
            asm volatile("ld.acquire.gpu.u32 %0, [%1];"
                         : "=r"(v) : "l"(&g_arrive) : "memory");
        } while (v < target);
    }
    __syncthreads();
}

__device__ __forceinline__ float sigf(float x) { return 1.f / (1.f + __expf(-x)); }

// =====================================================================
// Phase 1: Gx[s][row][b] = sum_k Wih[s][row][k] * x[b][s][k]
// grid (16 row-tiles, 64 s), 128 threads, 8x8 microtile, cp.async dbuf,
// 2 CTAs/SM for latency hiding. Resets phase-2 barrier counter.
// =====================================================================
#define AROW 68
#define P1_BUF ((64 + 128) * AROW)
#define P1_SMEM (2 * P1_BUF * 4)

__global__ __launch_bounds__(128, 2) void gemm_x_kernel(
    const float* __restrict__ x, const float* __restrict__ Wih) {
    extern __shared__ float sm[];
    const int tid = threadIdx.x;
    const int tb = tid & 7, tr = tid >> 3;
    const int jt = blockIdx.x, s = blockIdx.y;

    if (jt == 0 && s == 0 && tid == 0) g_arrive = 0;

    ull acc[8][8];
#pragma unroll
    for (int i = 0; i < 8; i++)
#pragma unroll
        for (int j = 0; j < 8; j++) acc[i][j] = 0ull;

    {
        float* base = sm;
#pragma unroll 4
        for (int p = 0; p < 8; p++) {
            int fi = tid + 128 * p, b = fi >> 4, f = fi & 15;
            cp16(smem_u32(base + b * AROW + f * 4),
                 x + ((size_t)b * SS + s) * IND + f * 4);
        }
#pragma unroll 4
        for (int p = 0; p < 16; p++) {
            int fi = tid + 128 * p, r = fi >> 4, f = fi & 15;
            cp16(smem_u32(base + 64 * AROW + r * AROW + f * 4),
                 Wih + ((size_t)s * G4 + jt * 128 + r) * IND + f * 4);
        }
        CP_COMMIT();
    }

    for (int c = 0; c < 8; c++) {
        CP_WAIT(0);
        __syncthreads();
        if (c + 1 < 8) {
            float* base = sm + ((c + 1) & 1) * P1_BUF;
            int k0 = (c + 1) * 64;
#pragma unroll 4
            for (int p = 0; p < 8; p++) {
                int fi = tid + 128 * p, b = fi >> 4, f = fi & 15;
                cp16(smem_u32(base + b * AROW + f * 4),
                     x + ((size_t)b * SS + s) * IND + k0 + f * 4);
            }
#pragma unroll 4
            for (int p = 0; p < 16; p++) {
                int fi = tid + 128 * p, r = fi >> 4, f = fi & 15;
                cp16(smem_u32(base + 64 * AROW + r * AROW + f * 4),
                     Wih + ((size_t)s * G4 + jt * 128 + r) * IND + k0 + f * 4);
            }
            CP_COMMIT();
        } else {
            CP_COMMIT();
        }

        const float* ab = sm + (c & 1) * P1_BUF + tb * AROW;
        const float* wb = sm + (c & 1) * P1_BUF + 64 * AROW + tr * AROW;
#pragma unroll 2
        for (int q = 0; q < 16; q++) {
            const int o = q * 4;
            ulonglong2 a2[8];
#pragma unroll
            for (int bb = 0; bb < 8; bb++)
                a2[bb] = *(const ulonglong2*)(ab + bb * (8 * AROW) + o);
#pragma unroll
            for (int rr = 0; rr < 8; rr++) {
                ulonglong2 w2 = *(const ulonglong2*)(wb + rr * (16 * AROW) + o);
#pragma unroll
                for (int bb = 0; bb < 8; bb++) {
                    ffma2(acc[bb][rr], a2[bb].x, w2.x);
                    ffma2(acc[bb][rr], a2[bb].y, w2.y);
                }
            }
        }
        __syncthreads();
    }

#pragma unroll
    for (int rr = 0; rr < 8; rr++) {
        int row = jt * 128 + tr + 16 * rr;
        float* dst = g_Gx + ((size_t)s * G4 + row) * BB + tb;
#pragma unroll
        for (int bb = 0; bb < 8; bb++) {
            float2 u = upk2(acc[bb][rr]);
            dst[8 * bb] = u.x + u.y;
        }
    }
}

// =====================================================================
// Phase 2: persistent recurrence, 128 CTAs x 256 threads.
// CTA owns 4 h-cols; warp = 8-batch group; lane = ks*4+j (8-way k-split).
// K pipelined in 2 halves of 256: lane slice = 32-k blocks ks and 8+ks.
// Layout: 32-float block m at row*HROW + 36*m (4-float skew), HROW=584
// (=8 mod 32): W LDS banks 8j+4ks conflict-free per quarter-warp; h 1wf.
// Epilogue via smem exchange -> coalesced float4 STG. red.release barrier.
// =====================================================================
#define HROW 584
#define SH_H (BB * HROW)                 // 37376 floats
#define WBUF (16 * HROW)                 // 9344 floats
#define SH_ST (SH_H + 2 * WBUF)          // exchange offset
#define P2_SMEM ((SH_ST + 256) * 4)      // 225280 B

// smem float offset for global k-float index kf (0..511): skew 4 per 32
#define SKOFS(kf) ((kf) + (((kf) >> 5) << 2))

__global__ __launch_bounds__(256, 1) void lstm_rec_kernel(
    const float* __restrict__ Whh, float* __restrict__ out) {
    extern __shared__ float sm[];
    float* sh_h  = sm;                  // [64][HROW]
    float* sh_W  = sm + SH_H;           // 2 x [16][HROW]
    float* sh_st = sm + SH_ST;          // [256] h exchange

    const int tid = threadIdx.x;
    const int w    = tid >> 5;
    const int lane = tid & 31;
    const int j    = lane & 3;
    const int ks   = lane >> 2;
    const int jh0  = blockIdx.x * 4;

    g_h[0][blockIdx.x * 256 + tid] = 0.f;

    // stage W[0] -> buffer 0
#pragma unroll 2
    for (int p = 0; p < 8; p++) {
        int fi = p * 256 + tid;
        int r = fi >> 7, kf = (fi & 127) * 4;
        int grow = (r >> 2) * 512 + jh0 + (r & 3);
        cp16(smem_u32(sh_W + r * HROW + SKOFS(kf)),
             Whh + (size_t)grow * HH + kf);
    }
    CP_COMMIT();

    float c[8];
#pragma unroll
    for (int u = 0; u < 8; u++) c[u] = 0.f;

    unsigned int target = NBLK;
    grid_sync_step(target);

    for (int s = 0; s < SS; s++) {
        const int cur = s & 1, nxt = cur ^ 1;

        const float* hsrc = g_h[cur];
        // h half A (k 0..255)
#pragma unroll 4
        for (int p = 0; p < 16; p++) {
            int fi = p * 256 + tid;                 // 0..4095
            int hb = fi >> 6, kf = (fi & 63) * 4;   // kf 0..252
            cp16(smem_u32(sh_h + hb * HROW + SKOFS(kf)), hsrc + hb * HH + kf);
        }
        CP_COMMIT();                                // group A
        // h half B (k 256..511)
#pragma unroll 4
        for (int p = 0; p < 16; p++) {
            int fi = p * 256 + tid;
            int hb = fi >> 6, kf = 256 + (fi & 63) * 4;
            cp16(smem_u32(sh_h + hb * HROW + SKOFS(kf)), hsrc + hb * HH + kf);
        }
        CP_COMMIT();                                // group B
        // W[s+1] prefetch
        if (s + 1 < SS) {
            const float* wsrc = Whh + (size_t)(s + 1) * G4 * HH;
            float* wdst = sh_W + nxt * WBUF;
#pragma unroll 2
            for (int p = 0; p < 8; p++) {
                int fi = p * 256 + tid;
                int r = fi >> 7, kf = (fi & 127) * 4;
                int grow = (r >> 2) * 512 + jh0 + (r & 3);
                cp16(smem_u32(wdst + r * HROW + SKOFS(kf)),
                     wsrc + (size_t)grow * HH + kf);
            }
        }
        CP_COMMIT();                                // group C

        ull acc[8][4];
#pragma unroll
        for (int bb = 0; bb < 8; bb++)
#pragma unroll
            for (int g = 0; g < 4; g++) acc[bb][g] = 0ull;

        const float* hb0 = sh_h + (w * 8) * HROW + 36 * ks;
        const float* wb0 = sh_W + cur * WBUF + j * HROW + 36 * ks;

        // ---- half A: wait A (leaves B, C in flight), compute 32-k slice ----
        CP_WAIT(2);
        __syncthreads();
#pragma unroll
        for (int q = 0; q < 8; q++) {
            const int o = q * 4;
            ulonglong2 w0 = *(const ulonglong2*)(wb0 + o);
            ulonglong2 w1 = *(const ulonglong2*)(wb0 + 4 * HROW + o);
            ulonglong2 w2 = *(const ulonglong2*)(wb0 + 8 * HROW + o);
            ulonglong2 w3 = *(const ulonglong2*)(wb0 + 12 * HROW + o);
#pragma unroll
            for (int bb = 0; bb < 8; bb++) {
                ulonglong2 h2 = *(const ulonglong2*)(hb0 + bb * HROW + o);
                ffma2(acc[bb][0], h2.x, w0.x); ffma2(acc[bb][0], h2.y, w0.y);
                ffma2(acc[bb][1], h2.x, w1.x); ffma2(acc[bb][1], h2.y, w1.y);
                ffma2(acc[bb][2], h2.x, w2.x); ffma2(acc[bb][2], h2.y, w2.y);
                ffma2(acc[bb][3], h2.x, w3.x); ffma2(acc[bb][3], h2.y, w3.y);
            }
        }

        // ---- half B: wait B (leaves C), compute second 32-k slice ----
        CP_WAIT(1);
        __syncthreads();
        const float* hb1 = hb0 + 288;               // block 8+ks = 36*8 floats on
        const float* wb1 = wb0 + 288;
#pragma unroll
        for (int q = 0; q < 8; q++) {
            const int o = q * 4;
            ulonglong2 w0 = *(const ulonglong2*)(wb1 + o);
            ulonglong2 w1 = *(const ulonglong2*)(wb1 + 4 * HROW + o);
            ulonglong2 w2 = *(const ulonglong2*)(wb1 + 8 * HROW + o);
            ulonglong2 w3 = *(const ulonglong2*)(wb1 + 12 * HROW + o);
#pragma unroll
            for (int bb = 0; bb < 8; bb++) {
                ulonglong2 h2 = *(const ulonglong2*)(hb1 + bb * HROW + o);
                ffma2(acc[bb][0], h2.x, w0.x); ffma2(acc[bb][0], h2.y, w0.y);
                ffma2(acc[bb][1], h2.x, w1.x); ffma2(acc[bb][1], h2.y, w1.y);
                ffma2(acc[bb][2], h2.x, w2.x); ffma2(acc[bb][2], h2.y, w2.y);
                ffma2(acc[bb][3], h2.x, w3.x); ffma2(acc[bb][3], h2.y, w3.y);
            }
        }

        // unpack
        float r[8][4];
#pragma unroll
        for (int bb = 0; bb < 8; bb++)
#pragma unroll
            for (int g = 0; g < 4; g++) {
                float2 u = upk2(acc[bb][g]);
                r[bb][g] = u.x + u.y;
            }

        // Gx prefetch (ks==0 lanes; overlaps shfl reduce)
        float gxa[4][8];
        if (ks == 0) {
            const float* gx = g_Gx + (size_t)s * G4 * BB;
#pragma unroll
            for (int g = 0; g < 4; g++) {
                const float* p = gx + (size_t)(g * 512 + jh0 + j) * BB + 8 * w;
                float4 lo = *(const float4*)(p);
                float4 hi = *(const float4*)(p + 4);
                gxa[g][0] = lo.x; gxa[g][1] = lo.y; gxa[g][2] = lo.z; gxa[g][3] = lo.w;
                gxa[g][4] = hi.x; gxa[g][5] = hi.y; gxa[g][6] = hi.z; gxa[g][7] = hi.w;
            }
        }

        // reduce over ks
#pragma unroll
        for (int m = 4; m <= 16; m <<= 1)
#pragma unroll
            for (int bb = 0; bb < 8; bb++)
#pragma unroll
                for (int g = 0; g < 4; g++)
                    r[bb][g] += __shfl_xor_sync(0xffffffffu, r[bb][g], m);

        // cell update -> exchange
        if (ks == 0) {
#pragma unroll
            for (int bb = 0; bb < 8; bb++) {
                float a0 = r[bb][0] + gxa[0][bb];
                float a1 = r[bb][1] + gxa[1][bb];
                float a2 = r[bb][2] + gxa[2][bb];
                float a3 = r[bb][3] + gxa[3][bb];
                float ig = sigf(a0);
                float fg = sigf(a1);
                float gg = tanhf(a2);
                float og = sigf(a3);
                c[bb] = fg * c[bb] + ig * gg;
                sh_st[(8 * w + bb) * 4 + j] = og * tanhf(c[bb]);
            }
        }
        __syncthreads();
        if (tid < 64) {                             // coalesced float4 h/out stores
            float4 hv4 = *(float4*)&sh_st[tid * 4];
            *(float4*)&g_h[nxt][tid * HH + jh0] = hv4;
            *(float4*)&out[((size_t)tid * SS + s) * HH + jh0] = hv4;
        }
        if (s + 1 < SS) {
            target += NBLK;
            grid_sync_step(target);
        }
    }
}

// ---------------------------------------------------------------------
extern "C" void kernel_launch(void* const* d_in, const int* in_sizes, int n_in,
                              void* d_out, int out_size) {
    const float* x   = (const float*)d_in[0];
    const float* Wih = (const float*)d_in[1];
    const float* Whh = (const float*)d_in[2];
    float* out = (float*)d_out;

    cudaFuncSetAttribute(gemm_x_kernel,
                         cudaFuncAttributeMaxDynamicSharedMemorySize, P1_SMEM);
    cudaFuncSetAttribute(lstm_rec_kernel,
                         cudaFuncAttributeMaxDynamicSharedMemorySize, P2_SMEM);

    dim3 g1(16, 64);
    gemm_x_kernel<<<g1, 128, P1_SMEM>>>(x, Wih);
    lstm_rec_kernel<<<NBLK, 256, P2_SMEM>>>(Whh, out);
}

// round 15
// speedup vs baseline: 1.9056x; 1.1823x over previous
#include <cuda_runtime.h>
#include <math.h>
#include <stdint.h>

#define BB 64      // batch
#define SS 64      // seq
#define IND 512    // input dim
#define HH 512     // hidden dim
#define G4 2048    // 4*H
#define NBLK 128   // persistent CTAs, phase 2

typedef unsigned long long ull;

// ---------------- packed fp32x2 (FFMA2) ----------------
__device__ __forceinline__ void ffma2(ull& d, ull a, ull b) {
    asm("fma.rn.f32x2 %0, %1, %2, %0;" : "+l"(d) : "l"(a), "l"(b));
}
__device__ __forceinline__ float2 upk2(ull v) {
    float2 r; asm("mov.b64 {%0, %1}, %2;" : "=f"(r.x), "=f"(r.y) : "l"(v)); return r;
}

// ---------------- cp.async ----------------
__device__ __forceinline__ uint32_t smem_u32(const void* p) {
    uint32_t a;
    asm("{ .reg .u64 t; cvta.to.shared.u64 t, %1; cvt.u32.u64 %0, t; }" : "=r"(a) : "l"(p));
    return a;
}
__device__ __forceinline__ void cp16(uint32_t dst, const void* src) {
    uint64_t g; asm("cvta.to.global.u64 %0, %1;" : "=l"(g) : "l"(src));
    asm volatile("cp.async.cg.shared.global [%0], [%1], 16;" :: "r"(dst), "l"(g) : "memory");
}
#define CP_COMMIT() asm volatile("cp.async.commit_group;" ::: "memory")
#define CP_WAIT(n)  asm volatile("cp.async.wait_group %0;" :: "n"(n) : "memory")

// ---------------- device scratch ----------------
__device__ float g_Gx[(size_t)SS * G4 * BB];   // [s][row=gate*512+col][b]
__device__ float g_h[2][BB * HH];
__device__ unsigned int g_arrive;              // monotonic barrier counter (reset by phase 1)

// grid barrier: no-return red.release arrive + acquire poll
__device__ __forceinline__ void grid_sync_step(unsigned int target) {
    __syncthreads();
    if (threadIdx.x == 0) {
        asm volatile("red.release.gpu.add.u32 [%0], 1;" :: "l"(&g_arrive) : "memory");
        unsigned int v;
        do {
            asm volatile("ld.acquire.gpu.u32 %0, [%1];"
                         : "=r"(v) : "l"(&g_arrive) : "memory");
        } while (v < target);
    }
    __syncthreads();
}

__device__ __forceinline__ float sigf(float x) { return 1.f / (1.f + __expf(-x)); }
// branch-free tanh: 1 - 2/(exp(2x)+1); exp->inf/0 degrade gracefully to +-1
__device__ __forceinline__ float tanhx(float x) {
    return 1.f - __fdividef(2.f, __expf(2.f * x) + 1.f);
}

// =====================================================================
// Phase 1: Gx[s][row][b] = sum_k Wih[s][row][k] * x[b][s][k]
// grid (16 row-tiles, 64 s), 128 threads, 8x8 microtile, cp.async dbuf,
// 2 CTAs/SM. Resets phase-2 barrier counter.
// =====================================================================
#define AROW 68
#define P1_BUF ((64 + 128) * AROW)
#define P1_SMEM (2 * P1_BUF * 4)

__global__ __launch_bounds__(128, 2) void gemm_x_kernel(
    const float* __restrict__ x, const float* __restrict__ Wih) {
    extern __shared__ float sm[];
    const int tid = threadIdx.x;
    const int tb = tid & 7, tr = tid >> 3;
    const int jt = blockIdx.x, s = blockIdx.y;

    if (jt == 0 && s == 0 && tid == 0) g_arrive = 0;

    ull acc[8][8];
#pragma unroll
    for (int i = 0; i < 8; i++)
#pragma unroll
        for (int j = 0; j < 8; j++) acc[i][j] = 0ull;

    {
        float* base = sm;
#pragma unroll 4
        for (int p = 0; p < 8; p++) {
            int fi = tid + 128 * p, b = fi >> 4, f = fi & 15;
            cp16(smem_u32(base + b * AROW + f * 4),
                 x + ((size_t)b * SS + s) * IND + f * 4);
        }
#pragma unroll 4
        for (int p = 0; p < 16; p++) {
            int fi = tid + 128 * p, r = fi >> 4, f = fi & 15;
            cp16(smem_u32(base + 64 * AROW + r * AROW + f * 4),
                 Wih + ((size_t)s * G4 + jt * 128 + r) * IND + f * 4);
        }
        CP_COMMIT();
    }

    for (int c = 0; c < 8; c++) {
        CP_WAIT(0);
        __syncthreads();
        if (c + 1 < 8) {
            float* base = sm + ((c + 1) & 1) * P1_BUF;
            int k0 = (c + 1) * 64;
#pragma unroll 4
            for (int p = 0; p < 8; p++) {
                int fi = tid + 128 * p, b = fi >> 4, f = fi & 15;
                cp16(smem_u32(base + b * AROW + f * 4),
                     x + ((size_t)b * SS + s) * IND + k0 + f * 4);
            }
#pragma unroll 4
            for (int p = 0; p < 16; p++) {
                int fi = tid + 128 * p, r = fi >> 4, f = fi & 15;
                cp16(smem_u32(base + 64 * AROW + r * AROW + f * 4),
                     Wih + ((size_t)s * G4 + jt * 128 + r) * IND + k0 + f * 4);
            }
            CP_COMMIT();
        } else {
            CP_COMMIT();
        }

        const float* ab = sm + (c & 1) * P1_BUF + tb * AROW;
        const float* wb = sm + (c & 1) * P1_BUF + 64 * AROW + tr * AROW;
#pragma unroll 2
        for (int q = 0; q < 16; q++) {
            const int o = q * 4;
            ulonglong2 a2[8];
#pragma unroll
            for (int bb = 0; bb < 8; bb++)
                a2[bb] = *(const ulonglong2*)(ab + bb * (8 * AROW) + o);
#pragma unroll
            for (int rr = 0; rr < 8; rr++) {
                ulonglong2 w2 = *(const ulonglong2*)(wb + rr * (16 * AROW) + o);
#pragma unroll
                for (int bb = 0; bb < 8; bb++) {
                    ffma2(acc[bb][rr], a2[bb].x, w2.x);
                    ffma2(acc[bb][rr], a2[bb].y, w2.y);
                }
            }
        }
        __syncthreads();
    }

#pragma unroll
    for (int rr = 0; rr < 8; rr++) {
        int row = jt * 128 + tr + 16 * rr;
        float* dst = g_Gx + ((size_t)s * G4 + row) * BB + tb;
#pragma unroll
        for (int bb = 0; bb < 8; bb++) {
            float2 u = upk2(acc[bb][rr]);
            dst[8 * bb] = u.x + u.y;
        }
    }
}

// =====================================================================
// Phase 2: persistent recurrence, 128 CTAs x 256 threads.
// CTA owns 4 h-cols; warp = 8-batch group; lane = ks*4+j.
// Per-warp h staging (own 8 rows only) -> syncwarp, no CTA syncs mid-step.
// K pipelined in 2 halves (blocks ks and 8+ks; block m at 36m, HROW=584).
// Epilogue distributed: lane (ks,j) owns cell (b=8w+ks, col jh0+j);
// Gx scalars prefetched at step start; SEL chain picks r[ks][*].
// =====================================================================
#define HROW 584
#define SH_H (BB * HROW)                 // 37376 floats
#define WBUF (16 * HROW)                 // 9344 floats
#define P2_SMEM ((SH_H + 2 * WBUF) * 4)  // 224256 B

#define SKOFS(kf) ((kf) + (((kf) >> 5) << 2))

__global__ __launch_bounds__(256, 1) void lstm_rec_kernel(
    const float* __restrict__ Whh, float* __restrict__ out) {
    extern __shared__ float sm[];
    float* sh_h = sm;                   // [64][HROW]
    float* sh_W = sm + SH_H;            // 2 x [16][HROW]

    const int tid  = threadIdx.x;
    const int w    = tid >> 5;
    const int lane = tid & 31;
    const int j    = lane & 3;
    const int ks   = lane >> 2;
    const int jh0  = blockIdx.x * 4;
    const int myb  = 8 * w + ks;        // this lane's batch
    const int jh   = jh0 + j;           // this lane's column

    g_h[0][blockIdx.x * 256 + tid] = 0.f;

    // stage W[0] -> buffer 0
#pragma unroll 2
    for (int p = 0; p < 8; p++) {
        int fi = p * 256 + tid;
        int r = fi >> 7, kf = (fi & 127) * 4;
        int grow = (r >> 2) * 512 + jh0 + (r & 3);
        cp16(smem_u32(sh_W + r * HROW + SKOFS(kf)),
             Whh + (size_t)grow * HH + kf);
    }
    CP_COMMIT();
    CP_WAIT(0);

    float c = 0.f;
    unsigned int target = NBLK;
    grid_sync_step(target);

    for (int s = 0; s < SS; s++) {
        const int cur = s & 1, nxt = cur ^ 1;

        // Gx scalar prefetch for this lane's cell (hidden across the step)
        const float* gxp = g_Gx + (size_t)s * G4 * BB;
        float gx0 = gxp[(size_t)(0 * 512 + jh) * BB + myb];
        float gx1 = gxp[(size_t)(1 * 512 + jh) * BB + myb];
        float gx2 = gxp[(size_t)(2 * 512 + jh) * BB + myb];
        float gx3 = gxp[(size_t)(3 * 512 + jh) * BB + myb];

        // per-warp h staging: warp w stages rows 8w..8w+7
        const float* hsrc = g_h[cur] + (w * 8) * HH;
        float* hdst = sh_h + (w * 8) * HROW;
        // half A (k 0..255)
#pragma unroll 4
        for (int p = 0; p < 16; p++) {
            int fi = p * 32 + lane;                 // 0..511
            int r8 = fi >> 6, kf = (fi & 63) * 4;   // kf 0..252
            cp16(smem_u32(hdst + r8 * HROW + SKOFS(kf)), hsrc + r8 * HH + kf);
        }
        CP_COMMIT();                                // group A
        // half B (k 256..511)
#pragma unroll 4
        for (int p = 0; p < 16; p++) {
            int fi = p * 32 + lane;
            int r8 = fi >> 6, kf = 256 + (fi & 63) * 4;
            cp16(smem_u32(hdst + r8 * HROW + SKOFS(kf)), hsrc + r8 * HH + kf);
        }
        CP_COMMIT();                                // group B
        // W[s+1] prefetch (CTA-spread; published by next grid barrier)
        if (s + 1 < SS) {
            const float* wsrc = Whh + (size_t)(s + 1) * G4 * HH;
            float* wdst = sh_W + nxt * WBUF;
#pragma unroll 2
            for (int p = 0; p < 8; p++) {
                int fi = p * 256 + tid;
                int r = fi >> 7, kf = (fi & 127) * 4;
                int grow = (r >> 2) * 512 + jh0 + (r & 3);
                cp16(smem_u32(wdst + r * HROW + SKOFS(kf)),
                     wsrc + (size_t)grow * HH + kf);
            }
        }
        CP_COMMIT();                                // group C

        ull acc[8][4];
#pragma unroll
        for (int bb = 0; bb < 8; bb++)
#pragma unroll
            for (int g = 0; g < 4; g++) acc[bb][g] = 0ull;

        const float* hb0 = sh_h + (w * 8) * HROW + 36 * ks;
        const float* wb0 = sh_W + cur * WBUF + j * HROW + 36 * ks;

        // ---- half A ----
        CP_WAIT(2);
        __syncwarp();
#pragma unroll
        for (int q = 0; q < 8; q++) {
            const int o = q * 4;
            ulonglong2 w0 = *(const ulonglong2*)(wb0 + o);
            ulonglong2 w1 = *(const ulonglong2*)(wb0 + 4 * HROW + o);
            ulonglong2 w2 = *(const ulonglong2*)(wb0 + 8 * HROW + o);
            ulonglong2 w3 = *(const ulonglong2*)(wb0 + 12 * HROW + o);
#pragma unroll
            for (int bb = 0; bb < 8; bb++) {
                ulonglong2 h2 = *(const ulonglong2*)(hb0 + bb * HROW + o);
                ffma2(acc[bb][0], h2.x, w0.x); ffma2(acc[bb][0], h2.y, w0.y);
                ffma2(acc[bb][1], h2.x, w1.x); ffma2(acc[bb][1], h2.y, w1.y);
                ffma2(acc[bb][2], h2.x, w2.x); ffma2(acc[bb][2], h2.y, w2.y);
                ffma2(acc[bb][3], h2.x, w3.x); ffma2(acc[bb][3], h2.y, w3.y);
            }
        }

        // ---- half B ----
        CP_WAIT(1);
        __syncwarp();
        const float* hb1 = hb0 + 288;
        const float* wb1 = wb0 + 288;
#pragma unroll
        for (int q = 0; q < 8; q++) {
            const int o = q * 4;
            ulonglong2 w0 = *(const ulonglong2*)(wb1 + o);
            ulonglong2 w1 = *(const ulonglong2*)(wb1 + 4 * HROW + o);
            ulonglong2 w2 = *(const ulonglong2*)(wb1 + 8 * HROW + o);
            ulonglong2 w3 = *(const ulonglong2*)(wb1 + 12 * HROW + o);
#pragma unroll
            for (int bb = 0; bb < 8; bb++) {
                ulonglong2 h2 = *(const ulonglong2*)(hb1 + bb * HROW + o);
                ffma2(acc[bb][0], h2.x, w0.x); ffma2(acc[bb][0], h2.y, w0.y);
                ffma2(acc[bb][1], h2.x, w1.x); ffma2(acc[bb][1], h2.y, w1.y);
                ffma2(acc[bb][2], h2.x, w2.x); ffma2(acc[bb][2], h2.y, w2.y);
                ffma2(acc[bb][3], h2.x, w3.x); ffma2(acc[bb][3], h2.y, w3.y);
            }
        }

        // unpack + full butterfly reduce over ks (leaves totals on ALL lanes)
        float r[8][4];
#pragma unroll
        for (int bb = 0; bb < 8; bb++)
#pragma unroll
            for (int g = 0; g < 4; g++) {
                float2 u = upk2(acc[bb][g]);
                r[bb][g] = u.x + u.y;
            }
#pragma unroll
        for (int m = 4; m <= 16; m <<= 1)
#pragma unroll
            for (int bb = 0; bb < 8; bb++)
#pragma unroll
                for (int g = 0; g < 4; g++)
                    r[bb][g] += __shfl_xor_sync(0xffffffffu, r[bb][g], m);

        // select this lane's batch (bb == ks) via SEL chain
        float a0 = r[0][0], a1 = r[0][1], a2 = r[0][2], a3 = r[0][3];
#pragma unroll
        for (int bb = 1; bb < 8; bb++)
            if (ks == bb) { a0 = r[bb][0]; a1 = r[bb][1]; a2 = r[bb][2]; a3 = r[bb][3]; }

        // cell update: one cell per lane
        a0 += gx0; a1 += gx1; a2 += gx2; a3 += gx3;
        float ig = sigf(a0);
        float fg = sigf(a1);
        float gg = tanhx(a2);
        float og = sigf(a3);
        c = fg * c + ig * gg;
        float hv = og * tanhx(c);
        g_h[nxt][myb * HH + jh] = hv;
        out[((size_t)myb * SS + s) * HH + jh] = hv;

        CP_WAIT(0);                     // own W[s+1] cp.async landed (long done)
        if (s + 1 < SS) {
            target += NBLK;
            grid_sync_step(target);     // syncthreads inside publishes W CTA-wide
        }
    }
}

// ---------------------------------------------------------------------
extern "C" void kernel_launch(void* const* d_in, const int* in_sizes, int n_in,
                              void* d_out, int out_size) {
    const float* x   = (const float*)d_in[0];
    const float* Wih = (const float*)d_in[1];
    const float* Whh = (const float*)d_in[2];
    float* out = (float*)d_out;

    cudaFuncSetAttribute(gemm_x_kernel,
                         cudaFuncAttributeMaxDynamicSharedMemorySize, P1_SMEM);
    cudaFuncSetAttribute(lstm_rec_kernel,
                         cudaFuncAttributeMaxDynamicSharedMemorySize, P2_SMEM);

    dim3 g1(16, 64);
    gemm_x_kernel<<<g1, 128, P1_SMEM>>>(x, Wih);
    lstm_rec_kernel<<<NBLK, 256, P2_SMEM>>>(Whh, out);
}